// round 3
// baseline (speedup 1.0000x reference)
#include <cuda_runtime.h>

// Problem constants (AttnSageGCN): B=32768 nodes, K=32 neighbors, D=128,
// HIDDEN=128 (4 heads x 32), H2=256 (K|V concat).
#define B_NODES 32768
#define KNBR 32
#define SCALE_ATTN 0.17677669529663687f

typedef unsigned long long ull;

// Scratch (device globals; no runtime allocation allowed)
__device__ float g_q[(size_t)B_NODES * 128];
__device__ float g_self[(size_t)B_NODES * 128];
__device__ float g_att[(size_t)B_NODES * 128];

// ---- packed f32x2 helpers (FFMA2 path: 2 MACs / SASS instr) ----
__device__ __forceinline__ ull pack2(float lo, float hi) {
    ull r; asm("mov.b64 %0, {%1, %2};" : "=l"(r) : "f"(lo), "f"(hi)); return r;
}
__device__ __forceinline__ float2 unpack2(ull v) {
    float2 f; asm("mov.b64 {%0, %1}, %2;" : "=f"(f.x), "=f"(f.y) : "l"(v)); return f;
}
__device__ __forceinline__ void fma2(ull& d, ull a, ull b) {
    asm("fma.rn.f32x2 %0, %1, %2, %0;" : "+l"(d) : "l"(a), "l"(b));
}

// =====================================================================
// Kernel 1: q = src @ wq + bq ; self = src @ w_self
// Combined GEMM (B,128) @ (128,256). Weights resident in SMEM.
// CTA = 32 rows. Thread tile = 8 rows x 4 cols (f32x2 over col pairs).
// =====================================================================
__global__ void __launch_bounds__(256, 1) k1_proj(
    const float* __restrict__ src, const float* __restrict__ wq,
    const float* __restrict__ bq, const float* __restrict__ wself)
{
    extern __shared__ float sm1[];
    float* W  = sm1;           // [128][256]
    float* bb = sm1 + 32768;   // [256]
    float* xs = sm1 + 33024;   // [32][128]
    int t = threadIdx.x;

    for (int i = t; i < 16384; i += 256) {
        int d = i >> 7, j = i & 127;
        W[d * 256 + j]       = wq[i];
        W[d * 256 + 128 + j] = wself[i];
    }
    if (t < 128) { bb[t] = bq[t]; bb[128 + t] = 0.f; }
    size_t row0 = (size_t)blockIdx.x * 32;
    for (int i = t * 4; i < 4096; i += 1024)
        *(float4*)&xs[i] = *(const float4*)&src[row0 * 128 + i];
    __syncthreads();

    int tj = t & 63, tk = t >> 6;     // warp-uniform tk -> broadcast xs reads
    int jb = tj * 4, rb = tk * 8;
    float4 bj = *(float4*)&bb[jb];
    ull acc[8][2];
#pragma unroll
    for (int i = 0; i < 8; i++) {
        acc[i][0] = pack2(bj.x, bj.y);
        acc[i][1] = pack2(bj.z, bj.w);
    }
#pragma unroll 4
    for (int d = 0; d < 128; d += 2) {
        ulonglong2 w0 = *(ulonglong2*)&W[d * 256 + jb];
        ulonglong2 w1 = *(ulonglong2*)&W[(d + 1) * 256 + jb];
#pragma unroll
        for (int i = 0; i < 8; i++) {
            float2 av = *(float2*)&xs[(rb + i) * 128 + d];
            ull a0 = pack2(av.x, av.x), a1 = pack2(av.y, av.y);
            fma2(acc[i][0], a0, w0.x); fma2(acc[i][1], a0, w0.y);
            fma2(acc[i][0], a1, w1.x); fma2(acc[i][1], a1, w1.y);
        }
    }
#pragma unroll
    for (int i = 0; i < 8; i++) {
        size_t r = row0 + rb + i;
        float2 u = unpack2(acc[i][0]), v = unpack2(acc[i][1]);
        float4 o = make_float4(u.x, u.y, v.x, v.y);
        if (jb < 128) *(float4*)&g_q[r * 128 + jb] = o;
        else          *(float4*)&g_self[r * 128 + (jb - 128)] = o;
    }
}

// =====================================================================
// Kernel 2 (dominant): persistent per-node. wkv stays in SMEM (128KB).
// Per node: kv = neighbors[b] @ wkv + bkv (32x256, K=128 inner),
// then 4-head single-query softmax attention -> g_att[b].
// Neighbor tile stored TRANSPOSED nT[d][k] so the k-dim is the packed
// f32x2 operand (LDS.128 direct, no packs); only wkv needs dup-packs.
// Thread tile: 8 k (4 pairs) x 4 j  -> 16 f32x2 accumulators.
// Next node's neighbors prefetched into registers before the GEMM.
// =====================================================================
#define NBRT_STRIDE 36   // 32 + pad, keeps LDS.128 alignment (kb in {0,8,16,24})
#define KV_STRIDE   258  // 256 + pad: breaks worst-case attention bank conflicts

__global__ void __launch_bounds__(256, 1) k2_attn(
    const float* __restrict__ nbr, const float* __restrict__ wkv,
    const float* __restrict__ bkv)
{
    extern __shared__ float sm2[];
    float* Wkv = sm2;            // [128][256]            32768 f
    float* nT  = sm2 + 32768;    // [2][128][NBRT_STRIDE]  9216 f
    float* kvs = sm2 + 41984;    // [32][KV_STRIDE]        8256 f
    float* qs  = sm2 + 50240;    // [128]
    float* ps  = sm2 + 50368;    // [128]
    float* bks = sm2 + 50496;    // [256]
    int t = threadIdx.x;

    for (int i = t * 4; i < 32768; i += 1024)
        *(float4*)&Wkv[i] = *(const float4*)&wkv[i];
    if (t < 64) *(float4*)&bks[t * 4] = *(const float4*)&bkv[t * 4];

    int kk = t >> 3;            // neighbor row this thread copies
    int dd = (t & 7) * 16;      // starting d of its 16 floats
    int b = blockIdx.x;
    if (b < B_NODES) {
        const float4* s4 = (const float4*)&nbr[((size_t)b * KNBR + kk) * 128 + dd];
#pragma unroll
        for (int c = 0; c < 4; c++) {
            float4 v = s4[c];
            nT[(dd + c * 4 + 0) * NBRT_STRIDE + kk] = v.x;
            nT[(dd + c * 4 + 1) * NBRT_STRIDE + kk] = v.y;
            nT[(dd + c * 4 + 2) * NBRT_STRIDE + kk] = v.z;
            nT[(dd + c * 4 + 3) * NBRT_STRIDE + kk] = v.w;
        }
    }
    __syncthreads();

    int tj = t & 63, tk = t >> 6;   // warp-uniform tk -> nT reads broadcast
    int jb = tj * 4, kb = tk * 8;
    int lane = t & 31, wh = t >> 5;
    int buf = 0;

    for (; b < B_NODES; b += gridDim.x) {
        int bn = b + gridDim.x;
        bool pf = bn < B_NODES;
        float4 pr0 = make_float4(0.f,0.f,0.f,0.f), pr1 = pr0, pr2 = pr0, pr3 = pr0;
        if (pf) {  // prefetch next node's neighbors; latency hidden by GEMM
            const float4* s4 = (const float4*)&nbr[((size_t)bn * KNBR + kk) * 128 + dd];
            pr0 = s4[0]; pr1 = s4[1]; pr2 = s4[2]; pr3 = s4[3];
        }
        if (t < 32)
            *(float4*)&qs[t * 4] = *(const float4*)&g_q[(size_t)b * 128 + t * 4];

        const float* nb = nT + buf * (128 * NBRT_STRIDE);
        float4 bj = *(float4*)&bks[jb];
        ull acc[4][4];
#pragma unroll
        for (int jc = 0; jc < 4; jc++) {
            float bv = (&bj.x)[jc];
            ull pv = pack2(bv, bv);
            acc[0][jc] = pv; acc[1][jc] = pv; acc[2][jc] = pv; acc[3][jc] = pv;
        }
#pragma unroll 4
        for (int d = 0; d < 128; d++) {
            ulonglong2 nA = *(ulonglong2*)&nb[d * NBRT_STRIDE + kb];      // k pairs 0,1
            ulonglong2 nB = *(ulonglong2*)&nb[d * NBRT_STRIDE + kb + 4];  // k pairs 2,3
            float4 w4 = *(const float4*)&Wkv[d * 256 + jb];
            ull w0 = pack2(w4.x, w4.x), w1 = pack2(w4.y, w4.y);
            ull w2 = pack2(w4.z, w4.z), w3 = pack2(w4.w, w4.w);
            fma2(acc[0][0], nA.x, w0); fma2(acc[1][0], nA.y, w0);
            fma2(acc[2][0], nB.x, w0); fma2(acc[3][0], nB.y, w0);
            fma2(acc[0][1], nA.x, w1); fma2(acc[1][1], nA.y, w1);
            fma2(acc[2][1], nB.x, w1); fma2(acc[3][1], nB.y, w1);
            fma2(acc[0][2], nA.x, w2); fma2(acc[1][2], nA.y, w2);
            fma2(acc[2][2], nB.x, w2); fma2(acc[3][2], nB.y, w2);
            fma2(acc[0][3], nA.x, w3); fma2(acc[1][3], nA.y, w3);
            fma2(acc[2][3], nB.x, w3); fma2(acc[3][3], nB.y, w3);
        }
        // spill kv tile to SMEM
#pragma unroll
        for (int kp = 0; kp < 4; kp++)
#pragma unroll
            for (int jc = 0; jc < 4; jc++) {
                float2 f = unpack2(acc[kp][jc]);
                kvs[(kb + 2 * kp)     * KV_STRIDE + jb + jc] = f.x;
                kvs[(kb + 2 * kp + 1) * KV_STRIDE + jb + jc] = f.y;
            }
        __syncthreads();

        // stage prefetched neighbors into the other buffer (transposed)
        if (pf) {
            float* dst = nT + (buf ^ 1) * (128 * NBRT_STRIDE);
            float4 vv;
            vv = pr0;
            dst[(dd + 0) * NBRT_STRIDE + kk] = vv.x; dst[(dd + 1) * NBRT_STRIDE + kk] = vv.y;
            dst[(dd + 2) * NBRT_STRIDE + kk] = vv.z; dst[(dd + 3) * NBRT_STRIDE + kk] = vv.w;
            vv = pr1;
            dst[(dd + 4) * NBRT_STRIDE + kk] = vv.x; dst[(dd + 5) * NBRT_STRIDE + kk] = vv.y;
            dst[(dd + 6) * NBRT_STRIDE + kk] = vv.z; dst[(dd + 7) * NBRT_STRIDE + kk] = vv.w;
            vv = pr2;
            dst[(dd + 8) * NBRT_STRIDE + kk] = vv.x; dst[(dd + 9) * NBRT_STRIDE + kk] = vv.y;
            dst[(dd +10) * NBRT_STRIDE + kk] = vv.z; dst[(dd +11) * NBRT_STRIDE + kk] = vv.w;
            vv = pr3;
            dst[(dd +12) * NBRT_STRIDE + kk] = vv.x; dst[(dd +13) * NBRT_STRIDE + kk] = vv.y;
            dst[(dd +14) * NBRT_STRIDE + kk] = vv.z; dst[(dd +15) * NBRT_STRIDE + kk] = vv.w;
        }

        // attention: warp wh (0..3) = head wh; lane = neighbor index
        if (wh < 4) {
            const float* kvr = &kvs[lane * KV_STRIDE + wh * 32];
            float lg = 0.f;
#pragma unroll
            for (int d = 0; d < 32; d += 2) {
                float2 qv = *(float2*)&qs[wh * 32 + d];
                float2 k2 = *(const float2*)&kvr[d];
                lg += qv.x * k2.x + qv.y * k2.y;
            }
            lg *= SCALE_ATTN;
            float m = lg;
#pragma unroll
            for (int off = 16; off > 0; off >>= 1)
                m = fmaxf(m, __shfl_xor_sync(0xffffffffu, m, off));
            float e = __expf(lg - m);
            float s = e;
#pragma unroll
            for (int off = 16; off > 0; off >>= 1)
                s += __shfl_xor_sync(0xffffffffu, s, off);
            ps[wh * 32 + lane] = e / s;
            __syncwarp();
            // lane = output dim d within head
            float o = 0.f;
#pragma unroll
            for (int k2 = 0; k2 < 32; k2++)
                o += ps[wh * 32 + k2] * kvs[k2 * KV_STRIDE + 128 + wh * 32 + lane];
            g_att[(size_t)b * 128 + wh * 32 + lane] = o;
        }
        __syncthreads();
        buf ^= 1;
    }
}

// =====================================================================
// Kernel 3: out = relu(g_self + g_att @ wo + bo). wo in SMEM.
// CTA = 64 rows. Thread tile = 8 rows x 4 cols.
// =====================================================================
__global__ void __launch_bounds__(256, 1) k3_out(
    const float* __restrict__ wo, const float* __restrict__ bo,
    float* __restrict__ out)
{
    extern __shared__ float sm3[];
    float* W  = sm3;            // [128][128]
    float* bb = sm3 + 16384;    // [128]
    float* os = sm3 + 16512;    // [64][128]
    int t = threadIdx.x;

    for (int i = t * 4; i < 16384; i += 1024)
        *(float4*)&W[i] = *(const float4*)&wo[i];
    if (t < 32) *(float4*)&bb[t * 4] = *(const float4*)&bo[t * 4];
    size_t row0 = (size_t)blockIdx.x * 64;
    for (int i = t * 4; i < 8192; i += 1024)
        *(float4*)&os[i] = *(const float4*)&g_att[row0 * 128 + i];
    __syncthreads();

    int tj = t & 31, tk = t >> 5;   // warp-uniform tk -> broadcast os reads
    int jb = tj * 4, rb = tk * 8;
    float4 bj = *(float4*)&bb[jb];
    ull acc[8][2];
#pragma unroll
    for (int i = 0; i < 8; i++) {
        acc[i][0] = pack2(bj.x, bj.y);
        acc[i][1] = pack2(bj.z, bj.w);
    }
#pragma unroll 4
    for (int d = 0; d < 128; d += 2) {
        ulonglong2 w0 = *(ulonglong2*)&W[d * 128 + jb];
        ulonglong2 w1 = *(ulonglong2*)&W[(d + 1) * 128 + jb];
#pragma unroll
        for (int i = 0; i < 8; i++) {
            float2 av = *(float2*)&os[(rb + i) * 128 + d];
            ull a0 = pack2(av.x, av.x), a1 = pack2(av.y, av.y);
            fma2(acc[i][0], a0, w0.x); fma2(acc[i][1], a0, w0.y);
            fma2(acc[i][0], a1, w1.x); fma2(acc[i][1], a1, w1.y);
        }
    }
#pragma unroll
    for (int i = 0; i < 8; i++) {
        size_t r = row0 + rb + i;
        float4 s4 = *(const float4*)&g_self[r * 128 + jb];
        float2 u = unpack2(acc[i][0]), v = unpack2(acc[i][1]);
        float4 o = make_float4(fmaxf(u.x + s4.x, 0.f), fmaxf(u.y + s4.y, 0.f),
                               fmaxf(v.x + s4.z, 0.f), fmaxf(v.y + s4.w, 0.f));
        *(float4*)&out[r * 128 + jb] = o;
    }
}

// =====================================================================
// Launch
// =====================================================================
#define K1_SMEM 148480   // 32768+256+4096 floats
#define K2_SMEM 203008   // 50752 floats
#define K3_SMEM 98816    // 24704 floats

extern "C" void kernel_launch(void* const* d_in, const int* in_sizes, int n_in,
                              void* d_out, int out_size)
{
    const float* src   = (const float*)d_in[0];
    const float* nbr   = (const float*)d_in[1];
    const float* wq    = (const float*)d_in[2];
    const float* bq    = (const float*)d_in[3];
    const float* wkv   = (const float*)d_in[4];
    const float* bkv   = (const float*)d_in[5];
    const float* wo    = (const float*)d_in[6];
    const float* bo    = (const float*)d_in[7];
    const float* wself = (const float*)d_in[8];
    float* out = (float*)d_out;

    cudaFuncSetAttribute(k1_proj, cudaFuncAttributeMaxDynamicSharedMemorySize, K1_SMEM);
    cudaFuncSetAttribute(k2_attn, cudaFuncAttributeMaxDynamicSharedMemorySize, K2_SMEM);
    cudaFuncSetAttribute(k3_out,  cudaFuncAttributeMaxDynamicSharedMemorySize, K3_SMEM);

    int dev = 0;
    cudaGetDevice(&dev);
    int nsm = 148;
    cudaDeviceGetAttribute(&nsm, cudaDevAttrMultiProcessorCount, dev);

    k1_proj<<<B_NODES / 32, 256, K1_SMEM>>>(src, wq, bq, wself);
    k2_attn<<<nsm, 256, K2_SMEM>>>(nbr, wkv, bkv);
    k3_out<<<B_NODES / 64, 256, K3_SMEM>>>(wo, bo, out);
}

// round 5
// speedup vs baseline: 1.7466x; 1.7466x over previous
#include <cuda_runtime.h>
#include <cuda_bf16.h>
#include <cstdint>

// AttnSageGCN: B=32768 nodes, K=32 neighbors, D=128, HIDDEN=128 (4x32), H2=256
#define B_NODES 32768
#define SCALE_ATTN 0.17677669529663687f
#define NT 8192   // k2 tiles: 4 nodes x 32 neighbors = 128 rows each

typedef unsigned long long ull;

// Scratch (device globals; no runtime allocation allowed)
__device__ float g_q[(size_t)B_NODES * 128];
__device__ float g_self[(size_t)B_NODES * 128];
__device__ float g_att[(size_t)B_NODES * 128];

// ---------------- packed f32x2 helpers (k1/k3 FFMA2 path) ----------------
__device__ __forceinline__ ull pack2(float lo, float hi) {
    ull r; asm("mov.b64 %0, {%1, %2};" : "=l"(r) : "f"(lo), "f"(hi)); return r;
}
__device__ __forceinline__ float2 unpack2(ull v) {
    float2 f; asm("mov.b64 {%0, %1}, %2;" : "=f"(f.x), "=f"(f.y) : "l"(v)); return f;
}
__device__ __forceinline__ void fma2(ull& d, ull a, ull b) {
    asm("fma.rn.f32x2 %0, %1, %2, %0;" : "+l"(d) : "l"(a), "l"(b));
}

// split fp32 pair -> packed bf16 hi + bf16 residual lo (memory order: a0=low half)
__device__ __forceinline__ void split2(float a0, float a1, unsigned& hi, unsigned& lo) {
    unsigned h;
    asm("cvt.rn.bf16x2.f32 %0, %1, %2;" : "=r"(h) : "f"(a1), "f"(a0));
    float h0 = __uint_as_float(h << 16);
    float h1 = __uint_as_float(h & 0xFFFF0000u);
    unsigned l;
    asm("cvt.rn.bf16x2.f32 %0, %1, %2;" : "=r"(l) : "f"(a1 - h1), "f"(a0 - h0));
    hi = h; lo = l;
}

// mma.sync m16n8k16 bf16 -> f32 (base-target PTX, compiles for compute_103)
__device__ __forceinline__ void mma16816(float* c, const unsigned* a, unsigned b0, unsigned b1) {
    asm("mma.sync.aligned.m16n8k16.row.col.f32.bf16.bf16.f32 "
        "{%0,%1,%2,%3}, {%4,%5,%6,%7}, {%8,%9}, {%0,%1,%2,%3};"
        : "+f"(c[0]), "+f"(c[1]), "+f"(c[2]), "+f"(c[3])
        : "r"(a[0]), "r"(a[1]), "r"(a[2]), "r"(a[3]), "r"(b0), "r"(b1));
}

// ---------------- k2 SMEM layout (bytes) ----------------
// Row stride for bf16 matrices: 136 halves = 272 bytes (conflict-free frag loads:
// bank(row,kpair) = (68*row + t) mod 32 = (4*row + t) mod 32 -> all distinct).
#define RSTR 272
#define OFF_BH  0         // wkv^T hi  [256][136] bf16   69632
#define OFF_BL  69632     // wkv^T lo                    69632
#define OFF_AH  139264    // A hi      [128][136] bf16   34816
#define OFF_AL  174080    // A lo                        34816
#define OFF_QS  208896    // q tile    512 f32            2048
#define OFF_BVS 210944    // V bias    128 f32             512
#define K2_SMEM 211456

__device__ __forceinline__ void storeA(char* sm, int t, const float4* pr) {
    int m = t >> 1, c0 = (t & 1) * 64;
    char* Ah = sm + OFF_AH;
    char* Al = sm + OFF_AL;
#pragma unroll
    for (int j = 0; j < 16; j++) {
        float4 u = pr[j];
        unsigned h0, l0, h1, l1;
        split2(u.x, u.y, h0, l0);
        split2(u.z, u.w, h1, l1);
        int cb = (c0 + j * 4) * 2;
        *(uint2*)(Ah + m * RSTR + cb) = make_uint2(h0, h1);
        *(uint2*)(Al + m * RSTR + cb) = make_uint2(l0, l1);
    }
}

// One phase of the split GEMM: acc += A x B[rows nb..nb+64) over K=128, 3 passes.
__device__ __forceinline__ void gemm_phase(const char* sm, float acc[2][8][4],
                                           int wm, int wn, int lane, int phase) {
    int g = lane >> 2, t4 = (lane & 3) * 2;
    int nb = phase * 128 + wn * 64;
#pragma unroll
    for (int pass = 0; pass < 3; pass++) {
        const char* Ap = sm + ((pass == 1) ? OFF_AL : OFF_AH);
        const char* Bp = sm + ((pass == 2) ? OFF_BL : OFF_BH);
#pragma unroll
        for (int ks = 0; ks < 8; ks++) {
            int kc = ks * 16 + t4;
            unsigned a[2][4];
#pragma unroll
            for (int mt = 0; mt < 2; mt++) {
                int r = wm * 32 + mt * 16 + g;
                a[mt][0] = *(const unsigned*)(Ap + r * RSTR + kc * 2);
                a[mt][1] = *(const unsigned*)(Ap + (r + 8) * RSTR + kc * 2);
                a[mt][2] = *(const unsigned*)(Ap + r * RSTR + (kc + 8) * 2);
                a[mt][3] = *(const unsigned*)(Ap + (r + 8) * RSTR + (kc + 8) * 2);
            }
#pragma unroll
            for (int nt = 0; nt < 8; nt++) {
                int n = nb + nt * 8 + g;
                unsigned b0 = *(const unsigned*)(Bp + n * RSTR + kc * 2);
                unsigned b1 = *(const unsigned*)(Bp + n * RSTR + (kc + 8) * 2);
                mma16816(acc[0][nt], a[0], b0, b1);
                mma16816(acc[1][nt], a[1], b0, b1);
            }
        }
    }
}

// =====================================================================
// Kernel 2: persistent mma.sync KV projection + fused per-node attention
//   Warp (wm, wn): node wm of the tile, output cols 64*wn (heads 2wn,2wn+1)
//   Phase 0 = K feats -> logits/softmax (p stays in registers)
//   Phase 1 = V feats -> weighted sum -> g_att
// =====================================================================
__global__ void __launch_bounds__(256, 1) k2_attn(
    const float* __restrict__ nbr, const float* __restrict__ wkv,
    const float* __restrict__ bkv)
{
    extern __shared__ char sm[];
    float* qsf = (float*)(sm + OFF_QS);
    float* bvs = (float*)(sm + OFF_BVS);
    int t = threadIdx.x, w = t >> 5, lane = t & 31;
    int wm = w >> 1, wn = w & 1;
    int g = lane >> 2, t4 = (lane & 3) * 2;

    // --- one-time: wkv -> SMEM bf16 hi/lo as B = wkv^T [n][k] ---
    {
        int n = t;
        char* BhP = sm + OFF_BH;
        char* BlP = sm + OFF_BL;
#pragma unroll 2
        for (int kc = 0; kc < 16; kc++) {
            float f[8];
#pragma unroll
            for (int j = 0; j < 8; j++) f[j] = wkv[(kc * 8 + j) * 256 + n];
            unsigned h0, h1, h2, h3, l0, l1, l2, l3;
            split2(f[0], f[1], h0, l0); split2(f[2], f[3], h1, l1);
            split2(f[4], f[5], h2, l2); split2(f[6], f[7], h3, l3);
            *(uint4*)(BhP + n * RSTR + kc * 16) = make_uint4(h0, h1, h2, h3);
            *(uint4*)(BlP + n * RSTR + kc * 16) = make_uint4(l0, l1, l2, l3);
        }
    }
    if (t < 32) *(float4*)&bvs[t * 4] = *(const float4*)&bkv[128 + t * 4];

    // --- prologue: tile0 A + q ---
    int tile = blockIdx.x;
    {
        int m = t >> 1, c0 = (t & 1) * 64;
        const float4* s4 = (const float4*)(nbr + (size_t)tile * 16384 + (size_t)m * 128 + c0);
        float4 pr[16];
#pragma unroll
        for (int j = 0; j < 16; j++) pr[j] = s4[j];
        storeA(sm, t, pr);
    }
    if (t < 128)
        *(float4*)&qsf[t * 4] = *(const float4*)&g_q[(size_t)tile * 512 + t * 4];
    __syncthreads();

    for (;;) {
        int ntile = tile + gridDim.x;
        bool pf = ntile < NT;
        float4 pr[16];
        float4 qpf = make_float4(0.f, 0.f, 0.f, 0.f);
        if (pf) {  // register prefetch; HBM latency hidden by the GEMM below
            int m = t >> 1, c0 = (t & 1) * 64;
            const float4* s4 = (const float4*)(nbr + (size_t)ntile * 16384 + (size_t)m * 128 + c0);
#pragma unroll
            for (int j = 0; j < 16; j++) pr[j] = s4[j];
            if (t < 128) qpf = *(const float4*)&g_q[(size_t)ntile * 512 + t * 4];
        }

        float acc[2][8][4];

        // ---------- Phase 0: K features ----------
#pragma unroll
        for (int mt = 0; mt < 2; mt++)
#pragma unroll
            for (int nt = 0; nt < 8; nt++)
#pragma unroll
                for (int i = 0; i < 4; i++) acc[mt][nt][i] = 0.f;
        gemm_phase(sm, acc, wm, wn, lane, 0);

        // logits: row = 16mt + 8rr + g, col = 64wn + 8nt + t4 + {0,1}
        float part[4][2];
#pragma unroll
        for (int s = 0; s < 4; s++) { part[s][0] = 0.f; part[s][1] = 0.f; }
        const float* q = qsf + wm * 128 + wn * 64;
#pragma unroll
        for (int nt = 0; nt < 8; nt++) {
            float2 qv = *(const float2*)&q[nt * 8 + t4];
            int hl = nt >> 2;
#pragma unroll
            for (int mt = 0; mt < 2; mt++)
#pragma unroll
                for (int rr = 0; rr < 2; rr++)
                    part[mt * 2 + rr][hl] += qv.x * acc[mt][nt][2 * rr]
                                           + qv.y * acc[mt][nt][2 * rr + 1];
        }
        float p[4][2];
#pragma unroll
        for (int hl = 0; hl < 2; hl++) {
            float lg[4];
#pragma unroll
            for (int s = 0; s < 4; s++) {
                float v = part[s][hl];
                v += __shfl_xor_sync(0xffffffffu, v, 1);
                v += __shfl_xor_sync(0xffffffffu, v, 2);
                lg[s] = v * SCALE_ATTN;
            }
            float mx = fmaxf(fmaxf(lg[0], lg[1]), fmaxf(lg[2], lg[3]));
            mx = fmaxf(mx, __shfl_xor_sync(0xffffffffu, mx, 4));
            mx = fmaxf(mx, __shfl_xor_sync(0xffffffffu, mx, 8));
            mx = fmaxf(mx, __shfl_xor_sync(0xffffffffu, mx, 16));
            float e0 = __expf(lg[0] - mx), e1 = __expf(lg[1] - mx);
            float e2 = __expf(lg[2] - mx), e3 = __expf(lg[3] - mx);
            float s = e0 + e1 + e2 + e3;
            s += __shfl_xor_sync(0xffffffffu, s, 4);
            s += __shfl_xor_sync(0xffffffffu, s, 8);
            s += __shfl_xor_sync(0xffffffffu, s, 16);
            float inv = 1.f / s;
            p[0][hl] = e0 * inv; p[1][hl] = e1 * inv;
            p[2][hl] = e2 * inv; p[3][hl] = e3 * inv;
        }

        // ---------- Phase 1: V features ----------
#pragma unroll
        for (int mt = 0; mt < 2; mt++)
#pragma unroll
            for (int nt = 0; nt < 8; nt++)
#pragma unroll
                for (int i = 0; i < 4; i++) acc[mt][nt][i] = 0.f;
        gemm_phase(sm, acc, wm, wn, lane, 1);

        {
            size_t node = (size_t)tile * 4 + wm;
#pragma unroll
            for (int nt = 0; nt < 8; nt++) {
                int hl = nt >> 2;
                float v0 = 0.f, v1 = 0.f;
#pragma unroll
                for (int mt = 0; mt < 2; mt++)
#pragma unroll
                    for (int rr = 0; rr < 2; rr++) {
                        float pv = p[mt * 2 + rr][hl];
                        v0 += pv * acc[mt][nt][2 * rr];
                        v1 += pv * acc[mt][nt][2 * rr + 1];
                    }
                v0 += __shfl_xor_sync(0xffffffffu, v0, 4);
                v0 += __shfl_xor_sync(0xffffffffu, v0, 8);
                v0 += __shfl_xor_sync(0xffffffffu, v0, 16);
                v1 += __shfl_xor_sync(0xffffffffu, v1, 4);
                v1 += __shfl_xor_sync(0xffffffffu, v1, 8);
                v1 += __shfl_xor_sync(0xffffffffu, v1, 16);
                if (g == 0) {
                    int c = wn * 64 + nt * 8 + t4;
                    float2 o = make_float2(v0 + bvs[c], v1 + bvs[c + 1]);
                    *(float2*)&g_att[node * 128 + c] = o;
                }
            }
        }

        if (!pf) break;
        __syncthreads();           // everyone done reading A/qs
        storeA(sm, t, pr);
        if (t < 128) *(float4*)&qsf[t * 4] = qpf;
        __syncthreads();
        tile = ntile;
    }
}

// =====================================================================
// Kernel 1 (persistent): q = src @ wq + bq ; self = src @ w_self
// =====================================================================
__global__ void __launch_bounds__(256, 1) k1_proj(
    const float* __restrict__ src, const float* __restrict__ wq,
    const float* __restrict__ bq, const float* __restrict__ wself)
{
    extern __shared__ float sm1[];
    float* W  = sm1;           // [128][256]
    float* bb = sm1 + 32768;   // [256]
    float* xs = sm1 + 33024;   // [32][128]
    int t = threadIdx.x;

    for (int i = t; i < 16384; i += 256) {
        int d = i >> 7, j = i & 127;
        W[d * 256 + j]       = wq[i];
        W[d * 256 + 128 + j] = wself[i];
    }
    if (t < 128) { bb[t] = bq[t]; bb[128 + t] = 0.f; }
    int c = blockIdx.x;
    {
        size_t r0 = (size_t)c * 4096;
        for (int i = t * 4; i < 4096; i += 1024)
            *(float4*)&xs[i] = *(const float4*)&src[r0 + i];
    }
    __syncthreads();

    int tj = t & 63, tk = t >> 6;
    int jb = tj * 4, rb = tk * 8;
    while (c < 1024) {
        int cn = c + gridDim.x;
        float4 pfr[4];
        if (cn < 1024) {
            const float4* s4 = (const float4*)&src[(size_t)cn * 4096 + t * 16];
#pragma unroll
            for (int i = 0; i < 4; i++) pfr[i] = s4[i];
        }
        float4 bj = *(float4*)&bb[jb];
        ull acc[8][2];
#pragma unroll
        for (int i = 0; i < 8; i++) {
            acc[i][0] = pack2(bj.x, bj.y);
            acc[i][1] = pack2(bj.z, bj.w);
        }
#pragma unroll 4
        for (int d = 0; d < 128; d += 2) {
            ulonglong2 w0 = *(ulonglong2*)&W[d * 256 + jb];
            ulonglong2 w1 = *(ulonglong2*)&W[(d + 1) * 256 + jb];
#pragma unroll
            for (int i = 0; i < 8; i++) {
                float2 av = *(float2*)&xs[(rb + i) * 128 + d];
                ull a0 = pack2(av.x, av.x), a1 = pack2(av.y, av.y);
                fma2(acc[i][0], a0, w0.x); fma2(acc[i][1], a0, w0.y);
                fma2(acc[i][0], a1, w1.x); fma2(acc[i][1], a1, w1.y);
            }
        }
        size_t row0 = (size_t)c * 32;
#pragma unroll
        for (int i = 0; i < 8; i++) {
            size_t r = row0 + rb + i;
            float2 u = unpack2(acc[i][0]), v = unpack2(acc[i][1]);
            float4 o = make_float4(u.x, u.y, v.x, v.y);
            if (jb < 128) *(float4*)&g_q[r * 128 + jb] = o;
            else          *(float4*)&g_self[r * 128 + (jb - 128)] = o;
        }
        __syncthreads();
        if (cn < 1024) {
#pragma unroll
            for (int i = 0; i < 4; i++) *(float4*)&xs[t * 16 + i * 4] = pfr[i];
        }
        __syncthreads();
        c = cn;
    }
}

// =====================================================================
// Kernel 3 (persistent): out = relu(g_self + g_att @ wo + bo)
// =====================================================================
__global__ void __launch_bounds__(256, 1) k3_out(
    const float* __restrict__ wo, const float* __restrict__ bo,
    float* __restrict__ out)
{
    extern __shared__ float sm3[];
    float* W  = sm3;            // [128][128]
    float* bb = sm3 + 16384;    // [128]
    float* os = sm3 + 16512;    // [64][128]
    int t = threadIdx.x;

    for (int i = t * 4; i < 16384; i += 1024)
        *(float4*)&W[i] = *(const float4*)&wo[i];
    if (t < 32) *(float4*)&bb[t * 4] = *(const float4*)&bo[t * 4];
    int c = blockIdx.x;
    {
        size_t r0 = (size_t)c * 8192;
        for (int i = t * 4; i < 8192; i += 1024)
            *(float4*)&os[i] = *(const float4*)&g_att[r0 + i];
    }
    __syncthreads();

    int tj = t & 31, tk = t >> 5;
    int jb = tj * 4, rb = tk * 8;
    while (c < 512) {
        int cn = c + gridDim.x;
        float4 pfr[8];
        if (cn < 512) {
            const float4* s4 = (const float4*)&g_att[(size_t)cn * 8192 + t * 32];
#pragma unroll
            for (int i = 0; i < 8; i++) pfr[i] = s4[i];
        }
        float4 bj = *(float4*)&bb[jb];
        ull acc[8][2];
#pragma unroll
        for (int i = 0; i < 8; i++) {
            acc[i][0] = pack2(bj.x, bj.y);
            acc[i][1] = pack2(bj.z, bj.w);
        }
#pragma unroll 4
        for (int d = 0; d < 128; d += 2) {
            ulonglong2 w0 = *(ulonglong2*)&W[d * 128 + jb];
            ulonglong2 w1 = *(ulonglong2*)&W[(d + 1) * 128 + jb];
#pragma unroll
            for (int i = 0; i < 8; i++) {
                float2 av = *(float2*)&os[(rb + i) * 128 + d];
                ull a0 = pack2(av.x, av.x), a1 = pack2(av.y, av.y);
                fma2(acc[i][0], a0, w0.x); fma2(acc[i][1], a0, w0.y);
                fma2(acc[i][0], a1, w1.x); fma2(acc[i][1], a1, w1.y);
            }
        }
        size_t row0 = (size_t)c * 64;
#pragma unroll
        for (int i = 0; i < 8; i++) {
            size_t r = row0 + rb + i;
            float4 s4 = *(const float4*)&g_self[r * 128 + jb];
            float2 u = unpack2(acc[i][0]), v = unpack2(acc[i][1]);
            float4 o = make_float4(fmaxf(u.x + s4.x, 0.f), fmaxf(u.y + s4.y, 0.f),
                                   fmaxf(v.x + s4.z, 0.f), fmaxf(v.y + s4.w, 0.f));
            *(float4*)&out[r * 128 + jb] = o;
        }
        __syncthreads();
        if (cn < 512) {
#pragma unroll
            for (int i = 0; i < 8; i++) *(float4*)&os[t * 32 + i * 4] = pfr[i];
        }
        __syncthreads();
        c = cn;
    }
}

// =====================================================================
// Launch
// =====================================================================
#define K1_SMEM 148480
#define K3_SMEM 98816

extern "C" void kernel_launch(void* const* d_in, const int* in_sizes, int n_in,
                              void* d_out, int out_size)
{
    const float* src   = (const float*)d_in[0];
    const float* nbr   = (const float*)d_in[1];
    const float* wq    = (const float*)d_in[2];
    const float* bq    = (const float*)d_in[3];
    const float* wkv   = (const float*)d_in[4];
    const float* bkv   = (const float*)d_in[5];
    const float* wo    = (const float*)d_in[6];
    const float* bo    = (const float*)d_in[7];
    const float* wself = (const float*)d_in[8];
    float* out = (float*)d_out;

    cudaFuncSetAttribute(k1_proj, cudaFuncAttributeMaxDynamicSharedMemorySize, K1_SMEM);
    cudaFuncSetAttribute(k2_attn, cudaFuncAttributeMaxDynamicSharedMemorySize, K2_SMEM);
    cudaFuncSetAttribute(k3_out,  cudaFuncAttributeMaxDynamicSharedMemorySize, K3_SMEM);

    int dev = 0;
    cudaGetDevice(&dev);
    int nsm = 148;
    cudaDeviceGetAttribute(&nsm, cudaDevAttrMultiProcessorCount, dev);

    k1_proj<<<nsm, 256, K1_SMEM>>>(src, wq, bq, wself);
    k2_attn<<<nsm, 256, K2_SMEM>>>(nbr, wkv, bkv);
    k3_out<<<nsm, 256, K3_SMEM>>>(wo, bo, out);
}

// round 8
// speedup vs baseline: 4.0663x; 2.3281x over previous
#include <cuda_runtime.h>
#include <cstdint>

// AttnSageGCN: B=32768 nodes, K=32 neighbors, D=128, HIDDEN=128 (4x32), H2=256
#define B_NODES 32768
#define SCALE_ATTN 0.17677669529663687f

typedef unsigned long long ull;

// Scratch (device globals; no runtime allocation allowed)
__device__ float g_q[(size_t)B_NODES * 128];
__device__ float g_self[(size_t)B_NODES * 128];
__device__ float g_z[(size_t)B_NODES * 512];    // per node, [h][d] (SCALE folded in)
__device__ float g_m[(size_t)B_NODES * 512];    // per node, [h][d]
__device__ float g_v[(size_t)B_NODES * 128];    // attention output before wo

// ---------------- packed f32x2 helpers (FFMA2) ----------------
__device__ __forceinline__ ull pack2(float lo, float hi) {
    ull r; asm("mov.b64 %0, {%1, %2};" : "=l"(r) : "f"(lo), "f"(hi)); return r;
}
__device__ __forceinline__ float2 unpack2(ull v) {
    float2 f; asm("mov.b64 {%0, %1}, %2;" : "=f"(f.x), "=f"(f.y) : "l"(v)); return f;
}
__device__ __forceinline__ void fma2(ull& d, ull a, ull b) {
    asm("fma.rn.f32x2 %0, %1, %2, %0;" : "+l"(d) : "l"(a), "l"(b));
}

// ---------------- cp.async helpers (base-target, sm_80+) ----------------
__device__ __forceinline__ uint32_t smem_u32(const void* p) {
    uint32_t a;
    asm("{ .reg .u64 t; cvta.to.shared.u64 t, %1; cvt.u32.u64 %0, t; }" : "=r"(a) : "l"(p));
    return a;
}
__device__ __forceinline__ void cp16(uint32_t dst, const void* src) {
    asm volatile("cp.async.cg.shared.global [%0], [%1], 16;" :: "r"(dst), "l"(src) : "memory");
}
#define CP_COMMIT() asm volatile("cp.async.commit_group;" ::: "memory")
#define CP_WAIT0()  asm volatile("cp.async.wait_group 0;" ::: "memory")

// =====================================================================
// Kernel 1 (persistent): q = src @ wq + bq ; self = src @ w_self
// =====================================================================
__global__ void __launch_bounds__(256, 1) k1_proj(
    const float* __restrict__ src, const float* __restrict__ wq,
    const float* __restrict__ bq, const float* __restrict__ wself)
{
    extern __shared__ float sm1[];
    float* W  = sm1;           // [128][256]
    float* bb = sm1 + 32768;   // [256]
    float* xs = sm1 + 33024;   // [32][128]
    int t = threadIdx.x;

    for (int i = t; i < 16384; i += 256) {
        int d = i >> 7, j = i & 127;
        W[d * 256 + j]       = wq[i];
        W[d * 256 + 128 + j] = wself[i];
    }
    if (t < 128) { bb[t] = bq[t]; bb[128 + t] = 0.f; }
    int c = blockIdx.x;
    {
        size_t r0 = (size_t)c * 4096;
        for (int i = t * 4; i < 4096; i += 1024)
            *(float4*)&xs[i] = *(const float4*)&src[r0 + i];
    }
    __syncthreads();

    int tj = t & 63, tk = t >> 6;
    int jb = tj * 4, rb = tk * 8;
    while (c < 1024) {
        int cn = c + gridDim.x;
        float4 pfr[4];
        if (cn < 1024) {
            const float4* s4 = (const float4*)&src[(size_t)cn * 4096 + t * 16];
#pragma unroll
            for (int i = 0; i < 4; i++) pfr[i] = s4[i];
        }
        float4 bj = *(float4*)&bb[jb];
        ull acc[8][2];
#pragma unroll
        for (int i = 0; i < 8; i++) {
            acc[i][0] = pack2(bj.x, bj.y);
            acc[i][1] = pack2(bj.z, bj.w);
        }
#pragma unroll 4
        for (int d = 0; d < 128; d += 2) {
            ulonglong2 w0 = *(ulonglong2*)&W[d * 256 + jb];
            ulonglong2 w1 = *(ulonglong2*)&W[(d + 1) * 256 + jb];
#pragma unroll
            for (int i = 0; i < 8; i++) {
                float2 av = *(float2*)&xs[(rb + i) * 128 + d];
                ull a0 = pack2(av.x, av.x), a1 = pack2(av.y, av.y);
                fma2(acc[i][0], a0, w0.x); fma2(acc[i][1], a0, w0.y);
                fma2(acc[i][0], a1, w1.x); fma2(acc[i][1], a1, w1.y);
            }
        }
        size_t row0 = (size_t)c * 32;
#pragma unroll
        for (int i = 0; i < 8; i++) {
            size_t r = row0 + rb + i;
            float2 u = unpack2(acc[i][0]), v = unpack2(acc[i][1]);
            float4 o = make_float4(u.x, u.y, v.x, v.y);
            if (jb < 128) *(float4*)&g_q[r * 128 + jb] = o;
            else          *(float4*)&g_self[r * 128 + (jb - 128)] = o;
        }
        __syncthreads();
        if (cn < 1024) {
#pragma unroll
            for (int i = 0; i < 4; i++) *(float4*)&xs[t * 16 + i * 4] = pfr[i];
        }
        __syncthreads();
        c = cn;
    }
}

// =====================================================================
// Kernel Z: z[b][h][d] = SCALE * sum_j q[b][32h+j] * Wk[d][32h+j]
// =====================================================================
#define ZT_STR 132
__global__ void __launch_bounds__(256, 2) kz_proj(const float* __restrict__ wkv)
{
    extern __shared__ float sz[];
    float* WT = sz;                  // [128 cols][132]: WT[c][d] = wkv[d][c]
    float* qs = sz + 128 * ZT_STR;   // [32][132]
    int t = threadIdx.x;

    {   // load + transpose Wk (coalesced global reads)
        int d = t >> 1, c0 = (t & 1) * 64;
#pragma unroll
        for (int i = 0; i < 16; i++) {
            float4 v = *(const float4*)&wkv[d * 256 + c0 + i * 4];
            WT[(c0 + i * 4 + 0) * ZT_STR + d] = v.x;
            WT[(c0 + i * 4 + 1) * ZT_STR + d] = v.y;
            WT[(c0 + i * 4 + 2) * ZT_STR + d] = v.z;
            WT[(c0 + i * 4 + 3) * ZT_STR + d] = v.w;
        }
    }
    size_t n0 = (size_t)blockIdx.x * 32;
    for (int i = t; i < 1024; i += 256) {   // q tile: 32 x 32 float4
        int gg = i >> 5, c4 = i & 31;
        *(float4*)&qs[gg * ZT_STR + c4 * 4] =
            *(const float4*)&g_q[(n0 + gg) * 128 + c4 * 4];
    }
    __syncthreads();

    int hd0 = (t & 63) * 8;
    int h = hd0 >> 7, d0 = hd0 & 127;
    int g0 = (t >> 6) * 8;
    ull acc[8][4];
#pragma unroll
    for (int gg = 0; gg < 8; gg++)
#pragma unroll
        for (int i = 0; i < 4; i++) acc[gg][i] = 0ULL;

#pragma unroll 4
    for (int j = 0; j < 32; j++) {
        const float* wr = &WT[(32 * h + j) * ZT_STR + d0];
        ulonglong2 w0 = *(const ulonglong2*)wr;
        ulonglong2 w1 = *(const ulonglong2*)(wr + 4);
#pragma unroll
        for (int gg = 0; gg < 8; gg++) {
            float qv = qs[(g0 + gg) * ZT_STR + 32 * h + j];
            ull qp = pack2(qv, qv);
            fma2(acc[gg][0], qp, w0.x); fma2(acc[gg][1], qp, w0.y);
            fma2(acc[gg][2], qp, w1.x); fma2(acc[gg][3], qp, w1.y);
        }
    }
#pragma unroll
    for (int gg = 0; gg < 8; gg++) {
        float2 a = unpack2(acc[gg][0]), b = unpack2(acc[gg][1]);
        float2 cc = unpack2(acc[gg][2]), dd = unpack2(acc[gg][3]);
        float4 o0 = make_float4(a.x * SCALE_ATTN, a.y * SCALE_ATTN,
                                b.x * SCALE_ATTN, b.y * SCALE_ATTN);
        float4 o1 = make_float4(cc.x * SCALE_ATTN, cc.y * SCALE_ATTN,
                                dd.x * SCALE_ATTN, dd.y * SCALE_ATTN);
        size_t base = (n0 + g0 + gg) * 512 + hd0;
        *(float4*)&g_z[base]     = o0;
        *(float4*)&g_z[base + 4] = o1;
    }
}

// =====================================================================
// Kernel 2: streaming attention. Warp-per-node.
//   logits[h][k] = n_k . z_h ; softmax over k (shfl); m_h = sum_k p n_k
// =====================================================================
#define NB_STR 132                    // floats per n row (pad)
#define NB_WARP (NB_STR * 32)         // 4224 floats per warp buffer
#define OFF_ZB  (NB_WARP * 8)         // 33792
#define OFF_PB  (OFF_ZB + 8 * 512)    // 37888
#define K2_SMEMF (OFF_PB + 8 * 128)   // 38912 floats = 155648 B

// FIXED: one row per iteration; 32 lanes x 16B = full 512B row.
__device__ __forceinline__ void k2_issue_rows(uint32_t nb_a, const float* nsrc,
                                              int lane, int i0, int i1) {
#pragma unroll
    for (int i = i0; i < i1; i++)
        cp16(nb_a + i * 528 + lane * 16, nsrc + i * 128 + lane * 4);
}

__global__ void __launch_bounds__(256, 1) k2_attn(const float* __restrict__ nbr)
{
    extern __shared__ float s2[];
    uint32_t sb = smem_u32(s2);
    int t = threadIdx.x, w = t >> 5, lane = t & 31;
    float* nb = s2 + w * NB_WARP;
    float* zb = s2 + OFF_ZB + w * 512;
    float* pb = s2 + OFF_PB + w * 128;
    uint32_t nb_a = sb + (w * NB_WARP) * 4;
    uint32_t zb_a = sb + (OFF_ZB + w * 512) * 4;

    int node = blockIdx.x * 8 + w;
    const int stride = gridDim.x * 8;

    if (node < B_NODES) {   // prologue: full n tile + z for node0
        const float* nsrc = nbr + (size_t)node * 4096;
        k2_issue_rows(nb_a, nsrc, lane, 0, 32);
        const float* zsrc = g_z + (size_t)node * 512 + lane * 16;
#pragma unroll
        for (int i = 0; i < 4; i++) cp16(zb_a + lane * 64 + i * 16, zsrc + i * 4);
        CP_COMMIT();
    }

    while (node < B_NODES) {
        int nxt = node + stride;
        CP_WAIT0();
        __syncwarp();

        // ---- logits: lane = neighbor k ----
        const float* row = nb + lane * NB_STR;
        ull lga[4], lgb[4];
#pragma unroll
        for (int h = 0; h < 4; h++) { lga[h] = 0ULL; lgb[h] = 0ULL; }
#pragma unroll 4
        for (int d4 = 0; d4 < 32; d4++) {
            ulonglong2 nv = *(const ulonglong2*)(row + d4 * 4);
#pragma unroll
            for (int h = 0; h < 4; h++) {
                ulonglong2 zv = *(const ulonglong2*)(zb + h * 128 + d4 * 4);
                fma2(lga[h], nv.x, zv.x);
                fma2(lgb[h], nv.y, zv.y);
            }
        }
        float p[4];
#pragma unroll
        for (int h = 0; h < 4; h++) {
            float2 a = unpack2(lga[h]), b = unpack2(lgb[h]);
            float lg = (a.x + a.y) + (b.x + b.y);
            float mx = lg;
#pragma unroll
            for (int o = 16; o > 0; o >>= 1)
                mx = fmaxf(mx, __shfl_xor_sync(0xffffffffu, mx, o));
            float e = __expf(lg - mx);
            float sum = e;
#pragma unroll
            for (int o = 16; o > 0; o >>= 1)
                sum += __shfl_xor_sync(0xffffffffu, sum, o);
            p[h] = e / sum;
        }
        *(float4*)&pb[lane * 4] = make_float4(p[0], p[1], p[2], p[3]);
        __syncwarp();

        // ---- m: lane owns d-chunk [4*lane, 4*lane+4) ----
        float4 mac[4];
#pragma unroll
        for (int h = 0; h < 4; h++) mac[h] = make_float4(0.f, 0.f, 0.f, 0.f);
#pragma unroll 4
        for (int k = 0; k < 16; k++) {
            float4 p4 = *(const float4*)&pb[k * 4];
            float4 nv = *(const float4*)&nb[k * NB_STR + 4 * lane];
            const float* pp = &p4.x;
#pragma unroll
            for (int h = 0; h < 4; h++) {
                mac[h].x = fmaf(pp[h], nv.x, mac[h].x);
                mac[h].y = fmaf(pp[h], nv.y, mac[h].y);
                mac[h].z = fmaf(pp[h], nv.z, mac[h].z);
                mac[h].w = fmaf(pp[h], nv.w, mac[h].w);
            }
        }
        if (nxt < B_NODES) {   // rows 0..15 consumed -> refill early
            __syncwarp();      // all lanes done reading rows 0..15
            k2_issue_rows(nb_a, nbr + (size_t)nxt * 4096, lane, 0, 16);
        }
#pragma unroll 4
        for (int k = 16; k < 32; k++) {
            float4 p4 = *(const float4*)&pb[k * 4];
            float4 nv = *(const float4*)&nb[k * NB_STR + 4 * lane];
            const float* pp = &p4.x;
#pragma unroll
            for (int h = 0; h < 4; h++) {
                mac[h].x = fmaf(pp[h], nv.x, mac[h].x);
                mac[h].y = fmaf(pp[h], nv.y, mac[h].y);
                mac[h].z = fmaf(pp[h], nv.z, mac[h].z);
                mac[h].w = fmaf(pp[h], nv.w, mac[h].w);
            }
        }
        if (nxt < B_NODES) {
            __syncwarp();      // all lanes done reading rows 16..31 and zb
            k2_issue_rows(nb_a, nbr + (size_t)nxt * 4096, lane, 16, 32);
            const float* zsrc = g_z + (size_t)nxt * 512 + lane * 16;
#pragma unroll
            for (int i = 0; i < 4; i++) cp16(zb_a + lane * 64 + i * 16, zsrc + i * 4);
            CP_COMMIT();
        }

        size_t mb = (size_t)node * 512;
#pragma unroll
        for (int h = 0; h < 4; h++)
            *(float4*)&g_m[mb + h * 128 + 4 * lane] = mac[h];

        node = nxt;
    }
}

// =====================================================================
// Kernel 3a: v[b][32h+c] = bv[32h+c] + sum_j m[b][h][j] * Wv[j][32h+c]
// =====================================================================
#define MV_STR 516
__global__ void __launch_bounds__(256, 1) k3a_v(
    const float* __restrict__ wkv, const float* __restrict__ bkv)
{
    extern __shared__ float sa[];
    float* Wv  = sa;                       // [128][132]
    float* ms  = sa + 128 * ZT_STR;        // [32][516]
    float* bvs = sa + 128 * ZT_STR + 32 * MV_STR;  // [128]
    int t = threadIdx.x;

    {
        int j = t >> 1, c0 = (t & 1) * 64;
#pragma unroll
        for (int i = 0; i < 16; i++)
            *(float4*)&Wv[j * ZT_STR + c0 + i * 4] =
                *(const float4*)&wkv[j * 256 + 128 + c0 + i * 4];
    }
    if (t < 32) *(float4*)&bvs[t * 4] = *(const float4*)&bkv[128 + t * 4];
    size_t n0 = (size_t)blockIdx.x * 32;
    for (int i = t; i < 4096; i += 256) {   // m tile: 32 x 128 float4
        int gg = i >> 7, c4 = i & 127;
        *(float4*)&ms[gg * MV_STR + c4 * 4] =
            *(const float4*)&g_m[(n0 + gg) * 512 + c4 * 4];
    }
    __syncthreads();

    int c0 = (t & 31) * 4, h = c0 >> 5, g0 = (t >> 5) * 4;
    float4 bv4 = *(float4*)&bvs[c0];
    ull acc[4][2];
#pragma unroll
    for (int gg = 0; gg < 4; gg++) {
        acc[gg][0] = pack2(bv4.x, bv4.y);
        acc[gg][1] = pack2(bv4.z, bv4.w);
    }
#pragma unroll 4
    for (int j = 0; j < 128; j++) {
        ulonglong2 w2 = *(const ulonglong2*)&Wv[j * ZT_STR + c0];
#pragma unroll
        for (int gg = 0; gg < 4; gg++) {
            float mv = ms[(g0 + gg) * MV_STR + h * 128 + j];
            ull mp = pack2(mv, mv);
            fma2(acc[gg][0], mp, w2.x);
            fma2(acc[gg][1], mp, w2.y);
        }
    }
#pragma unroll
    for (int gg = 0; gg < 4; gg++) {
        float2 u = unpack2(acc[gg][0]), v = unpack2(acc[gg][1]);
        *(float4*)&g_v[(n0 + g0 + gg) * 128 + c0] = make_float4(u.x, u.y, v.x, v.y);
    }
}

// =====================================================================
// Kernel 3b (persistent): out = relu(g_self + g_v @ wo + bo)
// =====================================================================
__global__ void __launch_bounds__(256, 1) k3_out(
    const float* __restrict__ wo, const float* __restrict__ bo,
    float* __restrict__ out)
{
    extern __shared__ float sm3[];
    float* W  = sm3;            // [128][128]
    float* bb = sm3 + 16384;    // [128]
    float* os = sm3 + 16512;    // [64][128]
    int t = threadIdx.x;

    for (int i = t * 4; i < 16384; i += 1024)
        *(float4*)&W[i] = *(const float4*)&wo[i];
    if (t < 32) *(float4*)&bb[t * 4] = *(const float4*)&bo[t * 4];
    int c = blockIdx.x;
    {
        size_t r0 = (size_t)c * 8192;
        for (int i = t * 4; i < 8192; i += 1024)
            *(float4*)&os[i] = *(const float4*)&g_v[r0 + i];
    }
    __syncthreads();

    int tj = t & 31, tk = t >> 5;
    int jb = tj * 4, rb = tk * 8;
    while (c < 512) {
        int cn = c + gridDim.x;
        float4 pfr[8];
        if (cn < 512) {
            const float4* s4 = (const float4*)&g_v[(size_t)cn * 8192 + t * 32];
#pragma unroll
            for (int i = 0; i < 8; i++) pfr[i] = s4[i];
        }
        float4 bj = *(float4*)&bb[jb];
        ull acc[8][2];
#pragma unroll
        for (int i = 0; i < 8; i++) {
            acc[i][0] = pack2(bj.x, bj.y);
            acc[i][1] = pack2(bj.z, bj.w);
        }
#pragma unroll 4
        for (int d = 0; d < 128; d += 2) {
            ulonglong2 w0 = *(ulonglong2*)&W[d * 128 + jb];
            ulonglong2 w1 = *(ulonglong2*)&W[(d + 1) * 128 + jb];
#pragma unroll
            for (int i = 0; i < 8; i++) {
                float2 av = *(float2*)&os[(rb + i) * 128 + d];
                ull a0 = pack2(av.x, av.x), a1 = pack2(av.y, av.y);
                fma2(acc[i][0], a0, w0.x); fma2(acc[i][1], a0, w0.y);
                fma2(acc[i][0], a1, w1.x); fma2(acc[i][1], a1, w1.y);
            }
        }
        size_t row0 = (size_t)c * 64;
#pragma unroll
        for (int i = 0; i < 8; i++) {
            size_t r = row0 + rb + i;
            float4 s4 = *(const float4*)&g_self[r * 128 + jb];
            float2 u = unpack2(acc[i][0]), v = unpack2(acc[i][1]);
            float4 o = make_float4(fmaxf(u.x + s4.x, 0.f), fmaxf(u.y + s4.y, 0.f),
                                   fmaxf(v.x + s4.z, 0.f), fmaxf(v.y + s4.w, 0.f));
            *(float4*)&out[r * 128 + jb] = o;
        }
        __syncthreads();
        if (cn < 512) {
#pragma unroll
            for (int i = 0; i < 8; i++) *(float4*)&os[t * 32 + i * 4] = pfr[i];
        }
        __syncthreads();
        c = cn;
    }
}

// =====================================================================
// Launch
// =====================================================================
#define K1_SMEM 148480
#define KZ_SMEM ((128 * ZT_STR + 32 * ZT_STR) * 4)                     // 84480
#define K2_SMEM (K2_SMEMF * 4)                                         // 155648
#define K3A_SMEM ((128 * ZT_STR + 32 * MV_STR + 128) * 4)              // 134144
#define K3_SMEM 98816

extern "C" void kernel_launch(void* const* d_in, const int* in_sizes, int n_in,
                              void* d_out, int out_size)
{
    const float* src   = (const float*)d_in[0];
    const float* nbr   = (const float*)d_in[1];
    const float* wq    = (const float*)d_in[2];
    const float* bq    = (const float*)d_in[3];
    const float* wkv   = (const float*)d_in[4];
    const float* bkv   = (const float*)d_in[5];
    const float* wo    = (const float*)d_in[6];
    const float* bo    = (const float*)d_in[7];
    const float* wself = (const float*)d_in[8];
    float* out = (float*)d_out;

    cudaFuncSetAttribute(k1_proj, cudaFuncAttributeMaxDynamicSharedMemorySize, K1_SMEM);
    cudaFuncSetAttribute(kz_proj, cudaFuncAttributeMaxDynamicSharedMemorySize, KZ_SMEM);
    cudaFuncSetAttribute(k2_attn, cudaFuncAttributeMaxDynamicSharedMemorySize, K2_SMEM);
    cudaFuncSetAttribute(k3a_v,   cudaFuncAttributeMaxDynamicSharedMemorySize, K3A_SMEM);
    cudaFuncSetAttribute(k3_out,  cudaFuncAttributeMaxDynamicSharedMemorySize, K3_SMEM);

    int dev = 0;
    cudaGetDevice(&dev);
    int nsm = 148;
    cudaDeviceGetAttribute(&nsm, cudaDevAttrMultiProcessorCount, dev);

    k1_proj<<<nsm, 256, K1_SMEM>>>(src, wq, bq, wself);
    kz_proj<<<1024, 256, KZ_SMEM>>>(wkv);
    k2_attn<<<nsm, 256, K2_SMEM>>>(nbr);
    k3a_v<<<1024, 256, K3A_SMEM>>>(wkv, bkv);
    k3_out<<<nsm, 256, K3_SMEM>>>(wo, bo, out);
}

// round 9
// speedup vs baseline: 4.8115x; 1.1833x over previous
#include <cuda_runtime.h>
#include <cstdint>

// AttnSageGCN: B=32768 nodes, K=32 neighbors, D=128, HIDDEN=128 (4x32), H2=256
#define B_NODES 32768
#define SCALE_ATTN 0.17677669529663687f

typedef unsigned long long ull;

// Scratch (device globals; no runtime allocation allowed)
__device__ float g_q[(size_t)B_NODES * 128];
__device__ float g_self[(size_t)B_NODES * 128];
__device__ float g_z[(size_t)B_NODES * 512];    // per node, [h][d] (SCALE folded in)
__device__ float g_m[(size_t)B_NODES * 512];    // per node, [h][d]
__device__ float g_v[(size_t)B_NODES * 128];    // attention output before wo

// ---------------- packed f32x2 helpers (FFMA2) ----------------
__device__ __forceinline__ ull pack2(float lo, float hi) {
    ull r; asm("mov.b64 %0, {%1, %2};" : "=l"(r) : "f"(lo), "f"(hi)); return r;
}
__device__ __forceinline__ float2 unpack2(ull v) {
    float2 f; asm("mov.b64 {%0, %1}, %2;" : "=f"(f.x), "=f"(f.y) : "l"(v)); return f;
}
__device__ __forceinline__ void fma2(ull& d, ull a, ull b) {
    asm("fma.rn.f32x2 %0, %1, %2, %0;" : "+l"(d) : "l"(a), "l"(b));
}

// ---------------- cp.async helpers (base-target, sm_80+) ----------------
__device__ __forceinline__ uint32_t smem_u32(const void* p) {
    uint32_t a;
    asm("{ .reg .u64 t; cvta.to.shared.u64 t, %1; cvt.u32.u64 %0, t; }" : "=r"(a) : "l"(p));
    return a;
}
__device__ __forceinline__ void cp16(uint32_t dst, const void* src) {
    asm volatile("cp.async.cg.shared.global [%0], [%1], 16;" :: "r"(dst), "l"(src) : "memory");
}
#define CP_COMMIT() asm volatile("cp.async.commit_group;" ::: "memory")
#define CP_WAIT0()  asm volatile("cp.async.wait_group 0;" ::: "memory")
#define CP_WAIT1()  asm volatile("cp.async.wait_group 1;" ::: "memory")

// =====================================================================
// Kernel 1 (persistent): q = src @ wq + bq ; self = src @ w_self
// =====================================================================
__global__ void __launch_bounds__(256, 1) k1_proj(
    const float* __restrict__ src, const float* __restrict__ wq,
    const float* __restrict__ bq, const float* __restrict__ wself)
{
    extern __shared__ float sm1[];
    float* W  = sm1;           // [128][256]
    float* bb = sm1 + 32768;   // [256]
    float* xs = sm1 + 33024;   // [32][128]
    int t = threadIdx.x;

    for (int i = t; i < 16384; i += 256) {
        int d = i >> 7, j = i & 127;
        W[d * 256 + j]       = wq[i];
        W[d * 256 + 128 + j] = wself[i];
    }
    if (t < 128) { bb[t] = bq[t]; bb[128 + t] = 0.f; }
    int c = blockIdx.x;
    {
        size_t r0 = (size_t)c * 4096;
        for (int i = t * 4; i < 4096; i += 1024)
            *(float4*)&xs[i] = *(const float4*)&src[r0 + i];
    }
    __syncthreads();

    int tj = t & 63, tk = t >> 6;
    int jb = tj * 4, rb = tk * 8;
    while (c < 1024) {
        int cn = c + gridDim.x;
        float4 pfr[4];
        if (cn < 1024) {
            const float4* s4 = (const float4*)&src[(size_t)cn * 4096 + t * 16];
#pragma unroll
            for (int i = 0; i < 4; i++) pfr[i] = s4[i];
        }
        float4 bj = *(float4*)&bb[jb];
        ull acc[8][2];
#pragma unroll
        for (int i = 0; i < 8; i++) {
            acc[i][0] = pack2(bj.x, bj.y);
            acc[i][1] = pack2(bj.z, bj.w);
        }
#pragma unroll 4
        for (int d = 0; d < 128; d += 2) {
            ulonglong2 w0 = *(ulonglong2*)&W[d * 256 + jb];
            ulonglong2 w1 = *(ulonglong2*)&W[(d + 1) * 256 + jb];
#pragma unroll
            for (int i = 0; i < 8; i++) {
                float2 av = *(float2*)&xs[(rb + i) * 128 + d];
                ull a0 = pack2(av.x, av.x), a1 = pack2(av.y, av.y);
                fma2(acc[i][0], a0, w0.x); fma2(acc[i][1], a0, w0.y);
                fma2(acc[i][0], a1, w1.x); fma2(acc[i][1], a1, w1.y);
            }
        }
        size_t row0 = (size_t)c * 32;
#pragma unroll
        for (int i = 0; i < 8; i++) {
            size_t r = row0 + rb + i;
            float2 u = unpack2(acc[i][0]), v = unpack2(acc[i][1]);
            float4 o = make_float4(u.x, u.y, v.x, v.y);
            if (jb < 128) *(float4*)&g_q[r * 128 + jb] = o;
            else          *(float4*)&g_self[r * 128 + (jb - 128)] = o;
        }
        __syncthreads();
        if (cn < 1024) {
#pragma unroll
            for (int i = 0; i < 4; i++) *(float4*)&xs[t * 16 + i * 4] = pfr[i];
        }
        __syncthreads();
        c = cn;
    }
}

// =====================================================================
// Kernel Z (persistent, cp.async double-buffered):
//   z[b][h][d] = SCALE * sum_j q[b][32h+j] * Wk[d][32h+j]
// =====================================================================
#define ZT_STR 132
#define KZ_QTILE (32 * ZT_STR)           // 4224 floats per q buffer
__global__ void __launch_bounds__(256, 2) kz_proj(const float* __restrict__ wkv)
{
    extern __shared__ float sz[];
    float* WT = sz;                      // [128 cols][132]: WT[c][d] = wkv[d][c]
    float* qs = sz + 128 * ZT_STR;       // 2 x [32][132]
    uint32_t qs_a = smem_u32(qs);
    int t = threadIdx.x;

    {   // load + transpose Wk (coalesced global reads)
        int d = t >> 1, c0 = (t & 1) * 64;
#pragma unroll
        for (int i = 0; i < 16; i++) {
            float4 v = *(const float4*)&wkv[d * 256 + c0 + i * 4];
            WT[(c0 + i * 4 + 0) * ZT_STR + d] = v.x;
            WT[(c0 + i * 4 + 1) * ZT_STR + d] = v.y;
            WT[(c0 + i * 4 + 2) * ZT_STR + d] = v.z;
            WT[(c0 + i * 4 + 3) * ZT_STR + d] = v.w;
        }
    }

    int row = t >> 3, seg = t & 7;       // q tile loader mapping
    int c = blockIdx.x;
    if (c < 1024) {
        const float* src = g_q + ((size_t)c * 32 + row) * 128 + seg * 16;
        uint32_t dst = qs_a + row * 528 + seg * 64;
#pragma unroll
        for (int i = 0; i < 4; i++) cp16(dst + i * 16, src + i * 4);
        CP_COMMIT();
    }
    __syncthreads();   // WT ready

    int hd0 = (t & 63) * 8;
    int h = hd0 >> 7, d0 = hd0 & 127;
    int g0 = (t >> 6) * 8;
    int buf = 0;

    while (c < 1024) {
        int cn = c + gridDim.x;
        if (cn < 1024) {
            const float* src = g_q + ((size_t)cn * 32 + row) * 128 + seg * 16;
            uint32_t dst = qs_a + (buf ^ 1) * (KZ_QTILE * 4) + row * 528 + seg * 64;
#pragma unroll
            for (int i = 0; i < 4; i++) cp16(dst + i * 16, src + i * 4);
            CP_COMMIT();
            CP_WAIT1();          // current buf's group complete
        } else {
            CP_WAIT0();
        }
        __syncthreads();

        const float* qsb = qs + buf * KZ_QTILE;
        size_t n0 = (size_t)c * 32;
        ull acc[8][4];
#pragma unroll
        for (int gg = 0; gg < 8; gg++)
#pragma unroll
            for (int i = 0; i < 4; i++) acc[gg][i] = 0ULL;

#pragma unroll 4
        for (int j = 0; j < 32; j++) {
            const float* wr = &WT[(32 * h + j) * ZT_STR + d0];
            ulonglong2 w0 = *(const ulonglong2*)wr;
            ulonglong2 w1 = *(const ulonglong2*)(wr + 4);
#pragma unroll
            for (int gg = 0; gg < 8; gg++) {
                float qv = qsb[(g0 + gg) * ZT_STR + 32 * h + j];
                ull qp = pack2(qv, qv);
                fma2(acc[gg][0], qp, w0.x); fma2(acc[gg][1], qp, w0.y);
                fma2(acc[gg][2], qp, w1.x); fma2(acc[gg][3], qp, w1.y);
            }
        }
#pragma unroll
        for (int gg = 0; gg < 8; gg++) {
            float2 a = unpack2(acc[gg][0]), b = unpack2(acc[gg][1]);
            float2 cc = unpack2(acc[gg][2]), dd = unpack2(acc[gg][3]);
            float4 o0 = make_float4(a.x * SCALE_ATTN, a.y * SCALE_ATTN,
                                    b.x * SCALE_ATTN, b.y * SCALE_ATTN);
            float4 o1 = make_float4(cc.x * SCALE_ATTN, cc.y * SCALE_ATTN,
                                    dd.x * SCALE_ATTN, dd.y * SCALE_ATTN);
            size_t base = (n0 + g0 + gg) * 512 + hd0;
            *(float4*)&g_z[base]     = o0;
            *(float4*)&g_z[base + 4] = o1;
        }
        __syncthreads();   // everyone done reading buf before it is refilled
        buf ^= 1; c = cn;
    }
}

// =====================================================================
// Kernel 2: streaming attention. Warp-per-node.
// =====================================================================
#define NB_STR 132                    // floats per n row (pad)
#define NB_WARP (NB_STR * 32)         // 4224 floats per warp buffer
#define OFF_ZB  (NB_WARP * 8)         // 33792
#define OFF_PB  (OFF_ZB + 8 * 512)    // 37888
#define K2_SMEMF (OFF_PB + 8 * 128)   // 38912 floats = 155648 B

__device__ __forceinline__ void k2_issue_rows(uint32_t nb_a, const float* nsrc,
                                              int lane, int i0, int i1) {
#pragma unroll
    for (int i = i0; i < i1; i++)
        cp16(nb_a + i * 528 + lane * 16, nsrc + i * 128 + lane * 4);
}

__global__ void __launch_bounds__(256, 1) k2_attn(const float* __restrict__ nbr)
{
    extern __shared__ float s2[];
    uint32_t sb = smem_u32(s2);
    int t = threadIdx.x, w = t >> 5, lane = t & 31;
    float* nb = s2 + w * NB_WARP;
    float* zb = s2 + OFF_ZB + w * 512;
    float* pb = s2 + OFF_PB + w * 128;
    uint32_t nb_a = sb + (w * NB_WARP) * 4;
    uint32_t zb_a = sb + (OFF_ZB + w * 512) * 4;

    int node = blockIdx.x * 8 + w;
    const int stride = gridDim.x * 8;

    if (node < B_NODES) {   // prologue: full n tile + z for node0
        const float* nsrc = nbr + (size_t)node * 4096;
        k2_issue_rows(nb_a, nsrc, lane, 0, 32);
        const float* zsrc = g_z + (size_t)node * 512 + lane * 16;
#pragma unroll
        for (int i = 0; i < 4; i++) cp16(zb_a + lane * 64 + i * 16, zsrc + i * 4);
        CP_COMMIT();
    }

    while (node < B_NODES) {
        int nxt = node + stride;
        CP_WAIT0();
        __syncwarp();

        // ---- logits: lane = neighbor k ----
        const float* row = nb + lane * NB_STR;
        ull lga[4], lgb[4];
#pragma unroll
        for (int h = 0; h < 4; h++) { lga[h] = 0ULL; lgb[h] = 0ULL; }
#pragma unroll 4
        for (int d4 = 0; d4 < 32; d4++) {
            ulonglong2 nv = *(const ulonglong2*)(row + d4 * 4);
#pragma unroll
            for (int h = 0; h < 4; h++) {
                ulonglong2 zv = *(const ulonglong2*)(zb + h * 128 + d4 * 4);
                fma2(lga[h], nv.x, zv.x);
                fma2(lgb[h], nv.y, zv.y);
            }
        }
        float p[4];
#pragma unroll
        for (int h = 0; h < 4; h++) {
            float2 a = unpack2(lga[h]), b = unpack2(lgb[h]);
            float lg = (a.x + a.y) + (b.x + b.y);
            float mx = lg;
#pragma unroll
            for (int o = 16; o > 0; o >>= 1)
                mx = fmaxf(mx, __shfl_xor_sync(0xffffffffu, mx, o));
            float e = __expf(lg - mx);
            float sum = e;
#pragma unroll
            for (int o = 16; o > 0; o >>= 1)
                sum += __shfl_xor_sync(0xffffffffu, sum, o);
            p[h] = e / sum;
        }
        *(float4*)&pb[lane * 4] = make_float4(p[0], p[1], p[2], p[3]);
        __syncwarp();

        // ---- m: lane owns d-chunk [4*lane, 4*lane+4) ----
        float4 mac[4];
#pragma unroll
        for (int h = 0; h < 4; h++) mac[h] = make_float4(0.f, 0.f, 0.f, 0.f);
#pragma unroll 4
        for (int k = 0; k < 16; k++) {
            float4 p4 = *(const float4*)&pb[k * 4];
            float4 nv = *(const float4*)&nb[k * NB_STR + 4 * lane];
            const float* pp = &p4.x;
#pragma unroll
            for (int h = 0; h < 4; h++) {
                mac[h].x = fmaf(pp[h], nv.x, mac[h].x);
                mac[h].y = fmaf(pp[h], nv.y, mac[h].y);
                mac[h].z = fmaf(pp[h], nv.z, mac[h].z);
                mac[h].w = fmaf(pp[h], nv.w, mac[h].w);
            }
        }
        if (nxt < B_NODES) {   // rows 0..15 consumed -> refill early
            __syncwarp();      // all lanes done reading rows 0..15
            k2_issue_rows(nb_a, nbr + (size_t)nxt * 4096, lane, 0, 16);
        }
#pragma unroll 4
        for (int k = 16; k < 32; k++) {
            float4 p4 = *(const float4*)&pb[k * 4];
            float4 nv = *(const float4*)&nb[k * NB_STR + 4 * lane];
            const float* pp = &p4.x;
#pragma unroll
            for (int h = 0; h < 4; h++) {
                mac[h].x = fmaf(pp[h], nv.x, mac[h].x);
                mac[h].y = fmaf(pp[h], nv.y, mac[h].y);
                mac[h].z = fmaf(pp[h], nv.z, mac[h].z);
                mac[h].w = fmaf(pp[h], nv.w, mac[h].w);
            }
        }
        if (nxt < B_NODES) {
            __syncwarp();      // all lanes done reading rows 16..31 and zb
            k2_issue_rows(nb_a, nbr + (size_t)nxt * 4096, lane, 16, 32);
            const float* zsrc = g_z + (size_t)nxt * 512 + lane * 16;
#pragma unroll
            for (int i = 0; i < 4; i++) cp16(zb_a + lane * 64 + i * 16, zsrc + i * 4);
            CP_COMMIT();
        }

        size_t mb = (size_t)node * 512;
#pragma unroll
        for (int h = 0; h < 4; h++)
            *(float4*)&g_m[mb + h * 128 + 4 * lane] = mac[h];

        node = nxt;
    }
}

// =====================================================================
// Kernel 3a (persistent, cp.async double-buffered):
//   v[b][32h+c] = bv[32h+c] + sum_j m[b][h][j] * Wv[j][32h+c]
// =====================================================================
#define MV_STR 516
#define MV_TILE (32 * MV_STR)           // 16512 floats per m buffer
__global__ void __launch_bounds__(256, 1) k3a_v(
    const float* __restrict__ wkv, const float* __restrict__ bkv)
{
    extern __shared__ float sa[];
    float* Wv  = sa;                                  // [128][132]
    float* ms  = sa + 128 * ZT_STR;                   // 2 x [32][516]
    float* bvs = sa + 128 * ZT_STR + 2 * MV_TILE;     // [128]
    uint32_t ms_a = smem_u32(ms);
    int t = threadIdx.x;

    {
        int j = t >> 1, c0w = (t & 1) * 64;
#pragma unroll
        for (int i = 0; i < 16; i++)
            *(float4*)&Wv[j * ZT_STR + c0w + i * 4] =
                *(const float4*)&wkv[j * 256 + 128 + c0w + i * 4];
    }
    if (t < 32) *(float4*)&bvs[t * 4] = *(const float4*)&bkv[128 + t * 4];

    int row = t >> 3, seg = t & 7;     // m tile loader: row, 64-float segment
    int c = blockIdx.x;
    if (c < 1024) {
        const float* src = g_m + ((size_t)c * 32 + row) * 512 + seg * 64;
        uint32_t dst = ms_a + row * 2064 + seg * 256;
#pragma unroll
        for (int i = 0; i < 16; i++) cp16(dst + i * 16, src + i * 4);
        CP_COMMIT();
    }
    __syncthreads();   // Wv/bvs ready

    int c0 = (t & 31) * 4, h = c0 >> 5, g0 = (t >> 5) * 4;
    float4 bv4 = *(float4*)&bvs[c0];
    int buf = 0;

    while (c < 1024) {
        int cn = c + gridDim.x;
        if (cn < 1024) {
            const float* src = g_m + ((size_t)cn * 32 + row) * 512 + seg * 64;
            uint32_t dst = ms_a + (buf ^ 1) * (MV_TILE * 4) + row * 2064 + seg * 256;
#pragma unroll
            for (int i = 0; i < 16; i++) cp16(dst + i * 16, src + i * 4);
            CP_COMMIT();
            CP_WAIT1();
        } else {
            CP_WAIT0();
        }
        __syncthreads();

        const float* msb = ms + buf * MV_TILE;
        size_t n0 = (size_t)c * 32;
        ull acc[4][2];
#pragma unroll
        for (int gg = 0; gg < 4; gg++) {
            acc[gg][0] = pack2(bv4.x, bv4.y);
            acc[gg][1] = pack2(bv4.z, bv4.w);
        }
#pragma unroll 4
        for (int j = 0; j < 128; j++) {
            ulonglong2 w2 = *(const ulonglong2*)&Wv[j * ZT_STR + c0];
#pragma unroll
            for (int gg = 0; gg < 4; gg++) {
                float mv = msb[(g0 + gg) * MV_STR + h * 128 + j];
                ull mp = pack2(mv, mv);
                fma2(acc[gg][0], mp, w2.x);
                fma2(acc[gg][1], mp, w2.y);
            }
        }
#pragma unroll
        for (int gg = 0; gg < 4; gg++) {
            float2 u = unpack2(acc[gg][0]), v = unpack2(acc[gg][1]);
            *(float4*)&g_v[(n0 + g0 + gg) * 128 + c0] = make_float4(u.x, u.y, v.x, v.y);
        }
        __syncthreads();   // all reads of buf done before refill
        buf ^= 1; c = cn;
    }
}

// =====================================================================
// Kernel 3b (persistent): out = relu(g_self + g_v @ wo + bo)
// =====================================================================
__global__ void __launch_bounds__(256, 1) k3_out(
    const float* __restrict__ wo, const float* __restrict__ bo,
    float* __restrict__ out)
{
    extern __shared__ float sm3[];
    float* W  = sm3;            // [128][128]
    float* bb = sm3 + 16384;    // [128]
    float* os = sm3 + 16512;    // [64][128]
    int t = threadIdx.x;

    for (int i = t * 4; i < 16384; i += 1024)
        *(float4*)&W[i] = *(const float4*)&wo[i];
    if (t < 32) *(float4*)&bb[t * 4] = *(const float4*)&bo[t * 4];
    int c = blockIdx.x;
    {
        size_t r0 = (size_t)c * 8192;
        for (int i = t * 4; i < 8192; i += 1024)
            *(float4*)&os[i] = *(const float4*)&g_v[r0 + i];
    }
    __syncthreads();

    int tj = t & 31, tk = t >> 5;
    int jb = tj * 4, rb = tk * 8;
    while (c < 512) {
        int cn = c + gridDim.x;
        float4 pfr[8];
        if (cn < 512) {
            const float4* s4 = (const float4*)&g_v[(size_t)cn * 8192 + t * 32];
#pragma unroll
            for (int i = 0; i < 8; i++) pfr[i] = s4[i];
        }
        float4 bj = *(float4*)&bb[jb];
        ull acc[8][2];
#pragma unroll
        for (int i = 0; i < 8; i++) {
            acc[i][0] = pack2(bj.x, bj.y);
            acc[i][1] = pack2(bj.z, bj.w);
        }
#pragma unroll 4
        for (int d = 0; d < 128; d += 2) {
            ulonglong2 w0 = *(ulonglong2*)&W[d * 128 + jb];
            ulonglong2 w1 = *(ulonglong2*)&W[(d + 1) * 128 + jb];
#pragma unroll
            for (int i = 0; i < 8; i++) {
                float2 av = *(float2*)&os[(rb + i) * 128 + d];
                ull a0 = pack2(av.x, av.x), a1 = pack2(av.y, av.y);
                fma2(acc[i][0], a0, w0.x); fma2(acc[i][1], a0, w0.y);
                fma2(acc[i][0], a1, w1.x); fma2(acc[i][1], a1, w1.y);
            }
        }
        size_t row0 = (size_t)c * 64;
#pragma unroll
        for (int i = 0; i < 8; i++) {
            size_t r = row0 + rb + i;
            float4 s4 = *(const float4*)&g_self[r * 128 + jb];
            float2 u = unpack2(acc[i][0]), v = unpack2(acc[i][1]);
            float4 o = make_float4(fmaxf(u.x + s4.x, 0.f), fmaxf(u.y + s4.y, 0.f),
                                   fmaxf(v.x + s4.z, 0.f), fmaxf(v.y + s4.w, 0.f));
            *(float4*)&out[r * 128 + jb] = o;
        }
        __syncthreads();
        if (cn < 512) {
#pragma unroll
            for (int i = 0; i < 8; i++) *(float4*)&os[t * 32 + i * 4] = pfr[i];
        }
        __syncthreads();
        c = cn;
    }
}

// =====================================================================
// Launch
// =====================================================================
#define K1_SMEM 148480
#define KZ_SMEM ((128 * ZT_STR + 2 * KZ_QTILE) * 4)                    // 101376
#define K2_SMEM (K2_SMEMF * 4)                                         // 155648
#define K3A_SMEM ((128 * ZT_STR + 2 * MV_TILE + 128) * 4)              // 199808
#define K3_SMEM 98816

extern "C" void kernel_launch(void* const* d_in, const int* in_sizes, int n_in,
                              void* d_out, int out_size)
{
    const float* src   = (const float*)d_in[0];
    const float* nbr   = (const float*)d_in[1];
    const float* wq    = (const float*)d_in[2];
    const float* bq    = (const float*)d_in[3];
    const float* wkv   = (const float*)d_in[4];
    const float* bkv   = (const float*)d_in[5];
    const float* wo    = (const float*)d_in[6];
    const float* bo    = (const float*)d_in[7];
    const float* wself = (const float*)d_in[8];
    float* out = (float*)d_out;

    cudaFuncSetAttribute(k1_proj, cudaFuncAttributeMaxDynamicSharedMemorySize, K1_SMEM);
    cudaFuncSetAttribute(kz_proj, cudaFuncAttributeMaxDynamicSharedMemorySize, KZ_SMEM);
    cudaFuncSetAttribute(k2_attn, cudaFuncAttributeMaxDynamicSharedMemorySize, K2_SMEM);
    cudaFuncSetAttribute(k3a_v,   cudaFuncAttributeMaxDynamicSharedMemorySize, K3A_SMEM);
    cudaFuncSetAttribute(k3_out,  cudaFuncAttributeMaxDynamicSharedMemorySize, K3_SMEM);

    int dev = 0;
    cudaGetDevice(&dev);
    int nsm = 148;
    cudaDeviceGetAttribute(&nsm, cudaDevAttrMultiProcessorCount, dev);

    k1_proj<<<nsm, 256, K1_SMEM>>>(src, wq, bq, wself);
    kz_proj<<<2 * nsm, 256, KZ_SMEM>>>(wkv);
    k2_attn<<<nsm, 256, K2_SMEM>>>(nbr);
    k3a_v<<<nsm, 256, K3A_SMEM>>>(wkv, bkv);
    k3_out<<<nsm, 256, K3_SMEM>>>(wo, bo, out);
}